// round 8
// baseline (speedup 1.0000x reference)
#include <cuda_runtime.h>
#include <math.h>
#include <stdint.h>

#define N_LEVELS   16
#define HASH_MASK  0x7FFFFu
#define TABLE_SIZE (1u << 19)
#define NB         32768          // 32^3 sort buckets
#define NMAX       (1 << 20)

struct HashParams {
    int   res[N_LEVELS];
    float resf[N_LEVELS];
    float rcpf[N_LEVELS];   // RN32(1/res), matching XLA's div->mul rewrite
};

__device__ unsigned g_count[NB];
__device__ unsigned g_cursor[NB];
__device__ int      g_perm[NMAX];
__device__ int      g_bkt[NMAX];
__device__ float4   g_xs[NMAX];    // clipped coords in sorted order

__device__ __forceinline__ float clipf(float v)
{
    return fminf(fmaxf(v, -1.0f), 1.0f);
}

__global__ void zero_kernel()
{
    int i = blockIdx.x * blockDim.x + threadIdx.x;
    if (i < NB) g_count[i] = 0;
}

// 4 points per thread: MLP on the atomics, caches bucket ids.
__global__ void hist_kernel(const float* __restrict__ x, int N)
{
    int base = (blockIdx.x * blockDim.x + threadIdx.x) * 4;
#pragma unroll
    for (int j = 0; j < 4; j++) {
        int n = base + j;
        if (n < N) {
            float x0 = clipf(x[n * 3 + 0]);
            float x1 = clipf(x[n * 3 + 1]);
            float x2 = clipf(x[n * 3 + 2]);
            int c0 = min(31, (int)((x0 + 1.0f) * 16.0f));
            int c1 = min(31, (int)((x1 + 1.0f) * 16.0f));
            int c2 = min(31, (int)((x2 + 1.0f) * 16.0f));
            int b = (c0 << 10) | (c1 << 5) | c2;
            g_bkt[n] = b;
            atomicAdd(&g_count[b], 1u);
        }
    }
}

// Single block, 1024 threads: exclusive scan of 32768 bucket counts.
__global__ void scan_kernel()
{
    __shared__ unsigned s[1024];
    int t = threadIdx.x;
    unsigned loc[32], sum = 0;
#pragma unroll
    for (int i = 0; i < 32; i++) { loc[i] = g_count[t * 32 + i]; sum += loc[i]; }
    s[t] = sum;
    __syncthreads();
    for (int d = 1; d < 1024; d <<= 1) {
        unsigned v = (t >= d) ? s[t - d] : 0u;
        __syncthreads();
        s[t] += v;
        __syncthreads();
    }
    unsigned pre = (t == 0) ? 0u : s[t - 1];
#pragma unroll
    for (int i = 0; i < 32; i++) { g_cursor[t * 32 + i] = pre; pre += loc[i]; }
}

// 4 points per thread; writes perm + sorted clipped coords.
__global__ void scatter_kernel(const float* __restrict__ x, int N)
{
    int base = (blockIdx.x * blockDim.x + threadIdx.x) * 4;
#pragma unroll
    for (int j = 0; j < 4; j++) {
        int n = base + j;
        if (n < N) {
            unsigned pos = atomicAdd(&g_cursor[g_bkt[n]], 1u);
            g_perm[pos] = n;
            float x0 = clipf(x[n * 3 + 0]);
            float x1 = clipf(x[n * 3 + 1]);
            float x2 = clipf(x[n * 3 + 2]);
            g_xs[pos] = make_float4(x0, x1, x2, 0.0f);
        }
    }
}

// ---------------------------------------------------------------------------
__global__ __launch_bounds__(256, 6)
void hash_encode_kernel(const float2* __restrict__ tables,
                        float4* __restrict__ out,
                        int N, HashParams p)
{
    int i = blockIdx.x * blockDim.x + threadIdx.x;
    if (i >= N) return;

    float4 xv4 = g_xs[i];          // coalesced, already clipped
    int    n   = g_perm[i];        // original point index (output row)
    float  xv[3] = {xv4.x, xv4.y, xv4.z};

    const unsigned PRIME[3] = {1u, 2654435761u, 805459861u};

    float4* o = out + (size_t)n * 8;

#pragma unroll
    for (int g = 0; g < 4; g++) {
        float accg[8];
#pragma unroll
        for (int li = 0; li < 4; li++) {
            const int   l    = 4 * g + li;
            const int   resi = p.res[l];
            const float resf = p.resf[l];
            const float rcp  = p.rcpf[l];
            const float2* __restrict__ tb = tables + (size_t)l * TABLE_SIZE;

            unsigned term[3][2];
            float    wgt[3][2];
#pragma unroll
            for (int d = 0; d < 3; d++) {
                float c  = xv[d] * resf;
                float cf = floorf(c);
                float lc = c - cf;
                int   ci = (int)cf;
                wgt[d][0] = 1.0f - lc;
                wgt[d][1] = lc;
#pragma unroll
                for (int b = 0; b < 2; b++) {
                    int m = ci + b;
                    if (m < 0)     m += resi;
                    if (m >= resi) m -= resi;
                    // corners_f = m * RN32(1/res)  (XLA div->mul rewrite)
                    float cfr = __fmul_rn((float)m, rcp);
                    // q = trunc(RN(cfr + 1) * 131072), two separate roundings
                    float t = __fmul_rn(__fadd_rn(cfr, 1.0f), 131072.0f);
                    term[d][b] = (unsigned)t * PRIME[d];
                }
            }

            float2 f[8];
            float  w[8];
#pragma unroll
            for (int k = 0; k < 8; k++) {
                int b0 = (k >> 2) & 1, b1 = (k >> 1) & 1, b2 = k & 1;
                unsigned h = (term[0][b0] + term[1][b1] + term[2][b2]) & HASH_MASK;
                f[k] = __ldg(tb + h);
                w[k] = wgt[0][b0] * wgt[1][b1] * wgt[2][b2];
            }
            float a0 = 0.0f, a1 = 0.0f;
#pragma unroll
            for (int k = 0; k < 8; k++) { a0 += w[k] * f[k].x; a1 += w[k] * f[k].y; }
            accg[2 * li]     = a0;
            accg[2 * li + 1] = a1;
        }
        o[2 * g]     = make_float4(accg[0], accg[1], accg[2], accg[3]);
        o[2 * g + 1] = make_float4(accg[4], accg[5], accg[6], accg[7]);
    }
}

// Fallback (no sort) for N > NMAX: identical math, reads x directly.
__global__ __launch_bounds__(256, 6)
void hash_encode_direct(const float* __restrict__ x,
                        const float2* __restrict__ tables,
                        float4* __restrict__ out,
                        int N, HashParams p)
{
    int n = blockIdx.x * blockDim.x + threadIdx.x;
    if (n >= N) return;
    float xv[3] = {clipf(x[n*3+0]), clipf(x[n*3+1]), clipf(x[n*3+2])};
    const unsigned PRIME[3] = {1u, 2654435761u, 805459861u};
    float4* o = out + (size_t)n * 8;
#pragma unroll
    for (int g = 0; g < 4; g++) {
        float accg[8];
#pragma unroll
        for (int li = 0; li < 4; li++) {
            const int l = 4 * g + li;
            const int resi = p.res[l];
            const float resf = p.resf[l], rcp = p.rcpf[l];
            const float2* __restrict__ tb = tables + (size_t)l * TABLE_SIZE;
            unsigned term[3][2]; float wgt[3][2];
#pragma unroll
            for (int d = 0; d < 3; d++) {
                float c = xv[d] * resf, cf = floorf(c), lc = c - cf;
                int ci = (int)cf;
                wgt[d][0] = 1.0f - lc; wgt[d][1] = lc;
#pragma unroll
                for (int b = 0; b < 2; b++) {
                    int m = ci + b;
                    if (m < 0) m += resi;
                    if (m >= resi) m -= resi;
                    float cfr = __fmul_rn((float)m, rcp);
                    float t = __fmul_rn(__fadd_rn(cfr, 1.0f), 131072.0f);
                    term[d][b] = (unsigned)t * PRIME[d];
                }
            }
            float2 f[8]; float w[8];
#pragma unroll
            for (int k = 0; k < 8; k++) {
                int b0 = (k >> 2) & 1, b1 = (k >> 1) & 1, b2 = k & 1;
                unsigned h = (term[0][b0] + term[1][b1] + term[2][b2]) & HASH_MASK;
                f[k] = __ldg(tb + h);
                w[k] = wgt[0][b0] * wgt[1][b1] * wgt[2][b2];
            }
            float a0 = 0.0f, a1 = 0.0f;
#pragma unroll
            for (int k = 0; k < 8; k++) { a0 += w[k]*f[k].x; a1 += w[k]*f[k].y; }
            accg[2*li] = a0; accg[2*li+1] = a1;
        }
        o[2*g]   = make_float4(accg[0], accg[1], accg[2], accg[3]);
        o[2*g+1] = make_float4(accg[4], accg[5], accg[6], accg[7]);
    }
}

extern "C" void kernel_launch(void* const* d_in, const int* in_sizes, int n_in,
                              void* d_out, int out_size)
{
    const float*  x      = (const float*)d_in[0];
    const float2* tables = (const float2*)d_in[1];
    float4*       out    = (float4*)d_out;

    int N = in_sizes[0] / 3;

    HashParams p;
    for (int i = 0; i < N_LEVELS; i++) {
        double r = 16.0 * pow(32.0, (double)i / 15.0);  // same libm as Python ref
        p.res[i]  = (int)r;
        p.resf[i] = (float)p.res[i];
        p.rcpf[i] = 1.0f / p.resf[i];
    }

    int threads = 256;
    if (N <= NMAX) {
        int qblocks = (N / 4 + threads - 1) / threads;
        zero_kernel<<<(NB + threads - 1) / threads, threads>>>();
        hist_kernel<<<qblocks, threads>>>(x, N);
        scan_kernel<<<1, 1024>>>();
        scatter_kernel<<<qblocks, threads>>>(x, N);
        hash_encode_kernel<<<(N + threads - 1) / threads, threads>>>(tables, out, N, p);
    } else {
        hash_encode_direct<<<(N + threads - 1) / threads, threads>>>(x, tables, out, N, p);
    }
}

// round 9
// speedup vs baseline: 1.0384x; 1.0384x over previous
#include <cuda_runtime.h>
#include <math.h>
#include <stdint.h>

#define N_LEVELS   16
#define HASH_MASK  0x7FFFFu
#define TABLE_SIZE (1u << 19)
#define NB         32768          // 32^3 sort buckets
#define NMAX       (1 << 20)

struct HashParams {
    int   res[N_LEVELS];
    float resf[N_LEVELS];
    float rcpf[N_LEVELS];   // RN32(1/res), matching XLA's div->mul rewrite
};

__device__ unsigned g_count[NB];
__device__ unsigned g_cursor[NB];
__device__ int      g_perm[NMAX];
__device__ int      g_bkt[NMAX];

__device__ __forceinline__ float clipf(float v)
{
    return fminf(fmaxf(v, -1.0f), 1.0f);
}

__global__ void zero_kernel()
{
    int i = blockIdx.x * blockDim.x + threadIdx.x;
    if (i < NB) g_count[i] = 0;
}

__global__ void hist_kernel(const float* __restrict__ x, int N)
{
    int n = blockIdx.x * blockDim.x + threadIdx.x;
    if (n >= N) return;
    float x0 = clipf(x[n * 3 + 0]);
    float x1 = clipf(x[n * 3 + 1]);
    float x2 = clipf(x[n * 3 + 2]);
    int c0 = min(31, (int)((x0 + 1.0f) * 16.0f));
    int c1 = min(31, (int)((x1 + 1.0f) * 16.0f));
    int c2 = min(31, (int)((x2 + 1.0f) * 16.0f));
    int b = (c0 << 10) | (c1 << 5) | c2;
    g_bkt[n] = b;
    atomicAdd(&g_count[b], 1u);
}

// Single block, 1024 threads: exclusive scan of 32768 bucket counts.
__global__ void scan_kernel()
{
    __shared__ unsigned s[1024];
    int t = threadIdx.x;
    unsigned loc[32], sum = 0;
#pragma unroll
    for (int i = 0; i < 32; i++) { loc[i] = g_count[t * 32 + i]; sum += loc[i]; }
    s[t] = sum;
    __syncthreads();
    for (int d = 1; d < 1024; d <<= 1) {
        unsigned v = (t >= d) ? s[t - d] : 0u;
        __syncthreads();
        s[t] += v;
        __syncthreads();
    }
    unsigned pre = (t == 0) ? 0u : s[t - 1];
#pragma unroll
    for (int i = 0; i < 32; i++) { g_cursor[t * 32 + i] = pre; pre += loc[i]; }
}

// 2 independent atomics per thread (latency hiding), perm write only.
__global__ void scatter_kernel(int N)
{
    int base = (blockIdx.x * blockDim.x + threadIdx.x) * 2;
#pragma unroll
    for (int j = 0; j < 2; j++) {
        int n = base + j;
        if (n < N) {
            unsigned pos = atomicAdd(&g_cursor[g_bkt[n]], 1u);
            g_perm[pos] = n;
        }
    }
}

// ---------------------------------------------------------------------------
__global__ __launch_bounds__(256)
void hash_encode_kernel(const float* __restrict__ x,
                        const float2* __restrict__ tables,
                        float* __restrict__ out,
                        int N, HashParams p)
{
    __shared__ float s_t[8][32 * 33];   // per-warp 32x32 transpose tile, pad 33

    int i   = blockIdx.x * blockDim.x + threadIdx.x;
    int wid = threadIdx.x >> 5;
    int lid = threadIdx.x & 31;

    bool valid = (i < N);
    int  ic    = valid ? i : (N - 1);
    int  n     = g_perm[ic];

    float xv[3] = {clipf(x[n * 3 + 0]), clipf(x[n * 3 + 1]), clipf(x[n * 3 + 2])};

    const unsigned PRIME[3] = {1u, 2654435761u, 805459861u};

    float acc[2 * N_LEVELS];

#pragma unroll
    for (int l = 0; l < N_LEVELS; l++) {
        const int   resi = p.res[l];
        const float resf = p.resf[l];
        const float rcp  = p.rcpf[l];
        const float2* __restrict__ tb = tables + (size_t)l * TABLE_SIZE;

        unsigned term[3][2];
        float    wgt[3][2];
#pragma unroll
        for (int d = 0; d < 3; d++) {
            float c  = xv[d] * resf;
            float cf = floorf(c);
            float lc = c - cf;
            int   ci = (int)cf;
            wgt[d][0] = 1.0f - lc;
            wgt[d][1] = lc;
#pragma unroll
            for (int b = 0; b < 2; b++) {
                int m = ci + b;
                if (m < 0)     m += resi;
                if (m >= resi) m -= resi;
                // corners_f = m * RN32(1/res)  (XLA div->mul rewrite)
                float cfr = __fmul_rn((float)m, rcp);
                // q = trunc(RN(cfr + 1) * 131072), two separate roundings
                float t = __fmul_rn(__fadd_rn(cfr, 1.0f), 131072.0f);
                term[d][b] = (unsigned)t * PRIME[d];
            }
        }

        float2 f[8];
        float  w[8];
#pragma unroll
        for (int k = 0; k < 8; k++) {
            int b0 = (k >> 2) & 1, b1 = (k >> 1) & 1, b2 = k & 1;
            unsigned h = (term[0][b0] + term[1][b1] + term[2][b2]) & HASH_MASK;
            f[k] = __ldg(tb + h);
            w[k] = wgt[0][b0] * wgt[1][b1] * wgt[2][b2];
        }
        float a0 = 0.0f, a1 = 0.0f;
#pragma unroll
        for (int k = 0; k < 8; k++) { a0 += w[k] * f[k].x; a1 += w[k] * f[k].y; }
        acc[2 * l]     = a0;
        acc[2 * l + 1] = a1;
    }

    // ---- warp-cooperative transposed store --------------------------------
    // Each point's output row is one 128B line; write it with ONE coalesced
    // warp-wide STG.32 instead of 8 scattered STG.128 (256 wf -> ~96 wf).
    float* sw = s_t[wid];
#pragma unroll
    for (int j = 0; j < 32; j++)
        sw[lid * 33 + j] = acc[j];        // stride 33: conflict-free
    __syncwarp();

    int  warp_i0 = i - lid;
    if (warp_i0 + 32 <= N) {
#pragma unroll 8
        for (int k = 0; k < 32; k++) {
            int nk = __shfl_sync(0xFFFFFFFFu, n, k);
            out[(size_t)nk * 32 + lid] = sw[k * 33 + lid];  // 1 line, 1 wf
        }
    } else if (valid) {
#pragma unroll
        for (int j = 0; j < 32; j++)
            out[(size_t)n * 32 + j] = acc[j];
    }
}

// Fallback (no sort) for N > NMAX: identical math, direct indexing.
__global__ __launch_bounds__(256)
void hash_encode_direct(const float* __restrict__ x,
                        const float2* __restrict__ tables,
                        float4* __restrict__ out,
                        int N, HashParams p)
{
    int n = blockIdx.x * blockDim.x + threadIdx.x;
    if (n >= N) return;
    float xv[3] = {clipf(x[n*3+0]), clipf(x[n*3+1]), clipf(x[n*3+2])};
    const unsigned PRIME[3] = {1u, 2654435761u, 805459861u};
    float4* o = out + (size_t)n * 8;
#pragma unroll
    for (int g = 0; g < 4; g++) {
        float accg[8];
#pragma unroll
        for (int li = 0; li < 4; li++) {
            const int l = 4 * g + li;
            const int resi = p.res[l];
            const float resf = p.resf[l], rcp = p.rcpf[l];
            const float2* __restrict__ tb = tables + (size_t)l * TABLE_SIZE;
            unsigned term[3][2]; float wgt[3][2];
#pragma unroll
            for (int d = 0; d < 3; d++) {
                float c = xv[d] * resf, cf = floorf(c), lc = c - cf;
                int ci = (int)cf;
                wgt[d][0] = 1.0f - lc; wgt[d][1] = lc;
#pragma unroll
                for (int b = 0; b < 2; b++) {
                    int m = ci + b;
                    if (m < 0) m += resi;
                    if (m >= resi) m -= resi;
                    float cfr = __fmul_rn((float)m, rcp);
                    float t = __fmul_rn(__fadd_rn(cfr, 1.0f), 131072.0f);
                    term[d][b] = (unsigned)t * PRIME[d];
                }
            }
            float2 f[8]; float w[8];
#pragma unroll
            for (int k = 0; k < 8; k++) {
                int b0 = (k >> 2) & 1, b1 = (k >> 1) & 1, b2 = k & 1;
                unsigned h = (term[0][b0] + term[1][b1] + term[2][b2]) & HASH_MASK;
                f[k] = __ldg(tb + h);
                w[k] = wgt[0][b0] * wgt[1][b1] * wgt[2][b2];
            }
            float a0 = 0.0f, a1 = 0.0f;
#pragma unroll
            for (int k = 0; k < 8; k++) { a0 += w[k]*f[k].x; a1 += w[k]*f[k].y; }
            accg[2*li] = a0; accg[2*li+1] = a1;
        }
        o[2*g]   = make_float4(accg[0], accg[1], accg[2], accg[3]);
        o[2*g+1] = make_float4(accg[4], accg[5], accg[6], accg[7]);
    }
}

extern "C" void kernel_launch(void* const* d_in, const int* in_sizes, int n_in,
                              void* d_out, int out_size)
{
    const float*  x      = (const float*)d_in[0];
    const float2* tables = (const float2*)d_in[1];

    int N = in_sizes[0] / 3;

    HashParams p;
    for (int i = 0; i < N_LEVELS; i++) {
        double r = 16.0 * pow(32.0, (double)i / 15.0);  // same libm as Python ref
        p.res[i]  = (int)r;
        p.resf[i] = (float)p.res[i];
        p.rcpf[i] = 1.0f / p.resf[i];
    }

    int threads = 256;
    if (N <= NMAX) {
        zero_kernel<<<(NB + threads - 1) / threads, threads>>>();
        hist_kernel<<<(N + threads - 1) / threads, threads>>>(x, N);
        scan_kernel<<<1, 1024>>>();
        scatter_kernel<<<((N + 1) / 2 + threads - 1) / threads, threads>>>(N);
        hash_encode_kernel<<<(N + threads - 1) / threads, threads>>>(
            x, tables, (float*)d_out, N, p);
    } else {
        hash_encode_direct<<<(N + threads - 1) / threads, threads>>>(
            x, tables, (float4*)d_out, N, p);
    }
}